// round 2
// baseline (speedup 1.0000x reference)
#include <cuda_runtime.h>
#include <cuda_bf16.h>

// Shapes (fixed per problem)
static constexpr int BATCH = 16;
static constexpr int CCH   = 512;
static constexpr int NPIX  = 4096;   // 64*64
static constexpr int HD    = 128;

// Scratch (device globals; no dynamic allocation allowed)
__device__ float g_logits[(size_t)3 * BATCH * HD * NPIX]; // [w][b][h][n], ~100MB
__device__ float g_G[BATCH * HD * HD];                    // [b][h][g]
__device__ float g_M2[BATCH * CCH * HD];                  // [b][c][g]
__device__ float g_s[CCH];
__device__ float g_t[CCH];

// ---------------------------------------------------------------------------
// prep: zero G, fold BN into scale/shift
// ---------------------------------------------------------------------------
__global__ void __launch_bounds__(256) k_prep(const float* __restrict__ gamma,
                                              const float* __restrict__ beta,
                                              const float* __restrict__ mean,
                                              const float* __restrict__ var) {
    int idx = blockIdx.x * 256 + threadIdx.x;
    if (idx < BATCH * HD * HD) g_G[idx] = 0.0f;
    if (idx < CCH) {
        float inv = rsqrtf(var[idx] + 1e-5f);
        float sc  = inv * gamma[idx];
        g_s[idx] = sc;
        g_t[idx] = beta[idx] - mean[idx] * sc;
    }
}

// ---------------------------------------------------------------------------
// K1: logits[w][b] = w_mat[w] (128x512) @ x[b] (512x4096)
// 128x128 tile, BK=16, 256 threads, 8x8 per-thread microtile
// ---------------------------------------------------------------------------
__global__ void __launch_bounds__(256) k_gemm_logits(const float* __restrict__ x,
                                                     const float* __restrict__ wA,
                                                     const float* __restrict__ wB,
                                                     const float* __restrict__ wC) {
    __shared__ float As[16][128];
    __shared__ float Bs[16][128];
    const int b  = blockIdx.z;
    const int w  = blockIdx.y;           // 0=A,1=B,2=C weight
    const int n0 = blockIdx.x * 128;
    const int tid = threadIdx.x;
    const int tx = tid & 15, ty = tid >> 4;

    const float* Wp = (w == 0) ? wA : (w == 1) ? wB : wC;
    const float* Xp = x + (size_t)b * CCH * NPIX;

    float acc[8][8];
#pragma unroll
    for (int i = 0; i < 8; i++)
#pragma unroll
        for (int j = 0; j < 8; j++) acc[i][j] = 0.0f;

    for (int k0 = 0; k0 < CCH; k0 += 16) {
#pragma unroll
        for (int s = tid; s < 512; s += 256) {
            // weight tile: 128 rows x 16 k, store transposed
            int row = s >> 2, kq = (s & 3) << 2;
            float4 v = *(const float4*)(Wp + (size_t)row * CCH + k0 + kq);
            As[kq + 0][row] = v.x; As[kq + 1][row] = v.y;
            As[kq + 2][row] = v.z; As[kq + 3][row] = v.w;
            // x tile: 16 k-rows x 128 n
            int kr = s >> 5, nq = (s & 31) << 2;
            *(float4*)&Bs[kr][nq] =
                *(const float4*)(Xp + (size_t)(k0 + kr) * NPIX + n0 + nq);
        }
        __syncthreads();
#pragma unroll
        for (int k = 0; k < 16; k++) {
            float a[8], bb[8];
            *(float4*)(a)      = *(const float4*)&As[k][ty * 8];
            *(float4*)(a + 4)  = *(const float4*)&As[k][ty * 8 + 4];
            *(float4*)(bb)     = *(const float4*)&Bs[k][tx * 8];
            *(float4*)(bb + 4) = *(const float4*)&Bs[k][tx * 8 + 4];
#pragma unroll
            for (int i = 0; i < 8; i++)
#pragma unroll
                for (int j = 0; j < 8; j++) acc[i][j] = fmaf(a[i], bb[j], acc[i][j]);
        }
        __syncthreads();
    }

    float* D = g_logits + ((size_t)(w * BATCH + b) * HD) * NPIX + n0;
#pragma unroll
    for (int i = 0; i < 8; i++) {
        int h = ty * 8 + i;
        float4 v0 = make_float4(acc[i][0], acc[i][1], acc[i][2], acc[i][3]);
        float4 v1 = make_float4(acc[i][4], acc[i][5], acc[i][6], acc[i][7]);
        *(float4*)(D + (size_t)h * NPIX + tx * 8)     = v0;
        *(float4*)(D + (size_t)h * NPIX + tx * 8 + 4) = v1;
    }
}

// ---------------------------------------------------------------------------
// K2: in-place row softmax over N=4096 for w=0 (A) and w=2 (C)
// one CTA (256 thr) per row
// ---------------------------------------------------------------------------
__global__ void __launch_bounds__(256) k_softmax() {
    int rid = blockIdx.x;                       // 0..4095
    int w = (rid < 2048) ? 0 : 2;
    int r = rid & 2047;                         // b*128 + h
    float* p = g_logits + ((size_t)(w * 2048 + r)) * NPIX;
    int tid = threadIdx.x;
    __shared__ float red[256];

    float4 v[4];
#pragma unroll
    for (int q = 0; q < 4; q++) v[q] = *(float4*)(p + (q * 256 + tid) * 4);

    float m = v[0].x;
#pragma unroll
    for (int q = 0; q < 4; q++) {
        m = fmaxf(m, v[q].x); m = fmaxf(m, v[q].y);
        m = fmaxf(m, v[q].z); m = fmaxf(m, v[q].w);
    }
    red[tid] = m; __syncthreads();
    for (int off = 128; off > 0; off >>= 1) {
        if (tid < off) red[tid] = fmaxf(red[tid], red[tid + off]);
        __syncthreads();
    }
    float M = red[0];
    __syncthreads();

    float ssum = 0.0f;
#pragma unroll
    for (int q = 0; q < 4; q++) {
        v[q].x = expf(v[q].x - M); ssum += v[q].x;
        v[q].y = expf(v[q].y - M); ssum += v[q].y;
        v[q].z = expf(v[q].z - M); ssum += v[q].z;
        v[q].w = expf(v[q].w - M); ssum += v[q].w;
    }
    red[tid] = ssum; __syncthreads();
    for (int off = 128; off > 0; off >>= 1) {
        if (tid < off) red[tid] += red[tid + off];
        __syncthreads();
    }
    float inv = 1.0f / red[0];
#pragma unroll
    for (int q = 0; q < 4; q++) {
        v[q].x *= inv; v[q].y *= inv; v[q].z *= inv; v[q].w *= inv;
        *(float4*)(p + (q * 256 + tid) * 4) = v[q];
    }
}

// ---------------------------------------------------------------------------
// K3: G[b] += Bf[b] (128x4096) @ A[b]^T   (K-split over n, atomicAdd)
// grid (16, 8): each CTA does a 512-wide n slice, full 128x128 output
// ---------------------------------------------------------------------------
__global__ void __launch_bounds__(256) k_gemm_G() {
    __shared__ float As[16][128];
    __shared__ float Bs[16][128];
    const int b  = blockIdx.x;
    const int nb = blockIdx.y * 512;
    const float* Bf = g_logits + ((size_t)(BATCH + b) * HD) * NPIX;   // w=1
    const float* Am = g_logits + ((size_t)b * HD) * NPIX;             // w=0 (softmaxed)
    const int tid = threadIdx.x;
    const int tx = tid & 15, ty = tid >> 4;

    float acc[8][8];
#pragma unroll
    for (int i = 0; i < 8; i++)
#pragma unroll
        for (int j = 0; j < 8; j++) acc[i][j] = 0.0f;

    for (int k0 = 0; k0 < 512; k0 += 16) {
#pragma unroll
        for (int s = tid; s < 512; s += 256) {
            int row = s >> 2, kq = (s & 3) << 2;
            float4 v = *(const float4*)(Bf + (size_t)row * NPIX + nb + k0 + kq);
            As[kq + 0][row] = v.x; As[kq + 1][row] = v.y;
            As[kq + 2][row] = v.z; As[kq + 3][row] = v.w;
            float4 u = *(const float4*)(Am + (size_t)row * NPIX + nb + k0 + kq);
            Bs[kq + 0][row] = u.x; Bs[kq + 1][row] = u.y;
            Bs[kq + 2][row] = u.z; Bs[kq + 3][row] = u.w;
        }
        __syncthreads();
#pragma unroll
        for (int k = 0; k < 16; k++) {
            float a[8], bb[8];
            *(float4*)(a)      = *(const float4*)&As[k][ty * 8];
            *(float4*)(a + 4)  = *(const float4*)&As[k][ty * 8 + 4];
            *(float4*)(bb)     = *(const float4*)&Bs[k][tx * 8];
            *(float4*)(bb + 4) = *(const float4*)&Bs[k][tx * 8 + 4];
#pragma unroll
            for (int i = 0; i < 8; i++)
#pragma unroll
                for (int j = 0; j < 8; j++) acc[i][j] = fmaf(a[i], bb[j], acc[i][j]);
        }
        __syncthreads();
    }
#pragma unroll
    for (int i = 0; i < 8; i++)
#pragma unroll
        for (int j = 0; j < 8; j++)
            atomicAdd(&g_G[((size_t)b * HD + ty * 8 + i) * HD + tx * 8 + j], acc[i][j]);
}

// ---------------------------------------------------------------------------
// K4: M2[b][c][g] = s[c] * sum_h wProj[c][h] * G[b][h][g]
// ---------------------------------------------------------------------------
__global__ void __launch_bounds__(128) k_M2(const float* __restrict__ wProj) {
    const int b = blockIdx.x, c = blockIdx.y, g = threadIdx.x;
    __shared__ float wrow[HD];
    wrow[g] = wProj[(size_t)c * HD + g];
    __syncthreads();
    const float* Gp = g_G + (size_t)b * HD * HD;
    float acc = 0.0f;
#pragma unroll 8
    for (int h = 0; h < HD; h++) acc = fmaf(wrow[h], Gp[h * HD + g], acc);
    g_M2[((size_t)b * CCH + c) * HD + g] = g_s[c] * acc;
}

// ---------------------------------------------------------------------------
// K5: out[b] = M2[b] (512x128) @ Cs[b] (128x4096) + t[c]
// ---------------------------------------------------------------------------
__global__ void __launch_bounds__(256) k_gemm_out(float* __restrict__ out) {
    __shared__ float As[16][128];
    __shared__ float Bs[16][128];
    const int b  = blockIdx.z;
    const int c0 = blockIdx.y * 128;
    const int n0 = blockIdx.x * 128;
    const float* Ap = g_M2 + (size_t)b * CCH * HD;
    const float* Cs = g_logits + ((size_t)(2 * BATCH + b) * HD) * NPIX; // w=2 (softmaxed)
    const int tid = threadIdx.x;
    const int tx = tid & 15, ty = tid >> 4;

    float acc[8][8];
#pragma unroll
    for (int i = 0; i < 8; i++)
#pragma unroll
        for (int j = 0; j < 8; j++) acc[i][j] = 0.0f;

    for (int k0 = 0; k0 < HD; k0 += 16) {
#pragma unroll
        for (int s = tid; s < 512; s += 256) {
            int row = s >> 2, kq = (s & 3) << 2;
            float4 v = *(const float4*)(Ap + (size_t)(c0 + row) * HD + k0 + kq);
            As[kq + 0][row] = v.x; As[kq + 1][row] = v.y;
            As[kq + 2][row] = v.z; As[kq + 3][row] = v.w;
            int kr = s >> 5, nq = (s & 31) << 2;
            *(float4*)&Bs[kr][nq] =
                *(const float4*)(Cs + (size_t)(k0 + kr) * NPIX + n0 + nq);
        }
        __syncthreads();
#pragma unroll
        for (int k = 0; k < 16; k++) {
            float a[8], bb[8];
            *(float4*)(a)      = *(const float4*)&As[k][ty * 8];
            *(float4*)(a + 4)  = *(const float4*)&As[k][ty * 8 + 4];
            *(float4*)(bb)     = *(const float4*)&Bs[k][tx * 8];
            *(float4*)(bb + 4) = *(const float4*)&Bs[k][tx * 8 + 4];
#pragma unroll
            for (int i = 0; i < 8; i++)
#pragma unroll
                for (int j = 0; j < 8; j++) acc[i][j] = fmaf(a[i], bb[j], acc[i][j]);
        }
        __syncthreads();
    }

#pragma unroll
    for (int i = 0; i < 8; i++) {
        int c = c0 + ty * 8 + i;
        float tc = g_t[c];
        float4 v0 = make_float4(acc[i][0] + tc, acc[i][1] + tc, acc[i][2] + tc, acc[i][3] + tc);
        float4 v1 = make_float4(acc[i][4] + tc, acc[i][5] + tc, acc[i][6] + tc, acc[i][7] + tc);
        float* D = out + ((size_t)b * CCH + c) * NPIX + n0 + tx * 8;
        *(float4*)(D)     = v0;
        *(float4*)(D + 4) = v1;
    }
}

// ---------------------------------------------------------------------------
extern "C" void kernel_launch(void* const* d_in, const int* in_sizes, int n_in,
                              void* d_out, int out_size) {
    const float* x     = (const float*)d_in[0];
    const float* wA    = (const float*)d_in[1];
    const float* wB    = (const float*)d_in[2];
    const float* wC    = (const float*)d_in[3];
    const float* wProj = (const float*)d_in[4];
    const float* gamma = (const float*)d_in[5];
    const float* beta  = (const float*)d_in[6];
    const float* mean  = (const float*)d_in[7];
    const float* var   = (const float*)d_in[8];
    float* out = (float*)d_out;

    k_prep<<<1024, 256>>>(gamma, beta, mean, var);
    k_gemm_logits<<<dim3(32, 3, BATCH), 256>>>(x, wA, wB, wC);
    k_softmax<<<4096, 256>>>();
    k_gemm_G<<<dim3(BATCH, 8), 256>>>();
    k_M2<<<dim3(BATCH, CCH), 128>>>(wProj);
    k_gemm_out<<<dim3(32, 4, BATCH), 256>>>(out);
}

// round 3
// speedup vs baseline: 1.3786x; 1.3786x over previous
#include <cuda_runtime.h>
#include <cuda_bf16.h>
#include <cstdint>

// Shapes (fixed per problem)
static constexpr int BATCH = 16;
static constexpr int CCH   = 512;
static constexpr int NPIX  = 4096;   // 64*64
static constexpr int HD    = 128;

// Scratch (device globals; no dynamic allocation allowed)
__device__ float g_logits[(size_t)3 * BATCH * HD * NPIX]; // [w][b][h][n], ~100MB
__device__ float g_G[BATCH * HD * HD];                    // [b][h][g]
__device__ float g_M2[BATCH * CCH * HD];                  // [b][c][g]
__device__ float g_s[CCH];
__device__ float g_t[CCH];

// ---------------------------------------------------------------------------
// helpers: tf32 rounding + m16n8k8 tf32 mma
// ---------------------------------------------------------------------------
__device__ __forceinline__ float tf32r(float x) {
    uint32_t u; asm("cvt.rna.tf32.f32 %0, %1;" : "=r"(u) : "f"(x));
    return __uint_as_float(u);
}
__device__ __forceinline__ void mma8(float4& d, const uint32_t* a, uint32_t b0, uint32_t b1) {
    asm volatile("mma.sync.aligned.m16n8k8.row.col.f32.tf32.tf32.f32 "
                 "{%0,%1,%2,%3},{%4,%5,%6,%7},{%8,%9},{%0,%1,%2,%3};"
                 : "+f"(d.x), "+f"(d.y), "+f"(d.z), "+f"(d.w)
                 : "r"(a[0]), "r"(a[1]), "r"(a[2]), "r"(a[3]), "r"(b0), "r"(b1));
}
__device__ __forceinline__ void split4(float4 v, float4& h, float4& l) {
    h.x = tf32r(v.x); l.x = tf32r(v.x - h.x);
    h.y = tf32r(v.y); l.y = tf32r(v.y - h.y);
    h.z = tf32r(v.z); l.z = tf32r(v.z - h.z);
    h.w = tf32r(v.w); l.w = tf32r(v.w - h.w);
}

static constexpr int SA = 20;   // [m][k] tile stride (16 + 4 pad)
static constexpr int SB = 136;  // [k][n] tile stride (128 + 8 pad)

// ---------------------------------------------------------------------------
// prep: zero G, fold BN into scale/shift
// ---------------------------------------------------------------------------
__global__ void __launch_bounds__(256) k_prep(const float* __restrict__ gamma,
                                              const float* __restrict__ beta,
                                              const float* __restrict__ mean,
                                              const float* __restrict__ var) {
    int idx = blockIdx.x * 256 + threadIdx.x;
    if (idx < BATCH * HD * HD) g_G[idx] = 0.0f;
    if (idx < CCH) {
        float inv = rsqrtf(var[idx] + 1e-5f);
        float sc  = inv * gamma[idx];
        g_s[idx] = sc;
        g_t[idx] = beta[idx] - mean[idx] * sc;
    }
}

// ---------------------------------------------------------------------------
// K1: logits[w][b] = w_mat[w] (128x512) @ x[b] (512x4096)   [tf32x3 tensor]
// CTA tile 128x128, BK=16, 8 warps (4 Mx2 N), warp tile 32x64
// ---------------------------------------------------------------------------
__global__ void __launch_bounds__(256) k_gemm_logits_t(const float* __restrict__ x,
                                                       const float* __restrict__ wA,
                                                       const float* __restrict__ wB,
                                                       const float* __restrict__ wC) {
    __shared__ float AsH[128 * SA], AsL[128 * SA];   // [m][k]
    __shared__ float BsH[16 * SB],  BsL[16 * SB];    // [k][n]
    const int b  = blockIdx.z;
    const int w  = blockIdx.y;
    const int n0 = blockIdx.x * 128;
    const int tid  = threadIdx.x;
    const int lane = tid & 31, wid = tid >> 5;
    const int wm = wid & 3, wn = wid >> 2;
    const int lm = lane >> 2, lk = lane & 3;

    const float* Wp = (w == 0) ? wA : (w == 1) ? wB : wC;
    const float* Xp = x + (size_t)b * CCH * NPIX;

    float4 acc[2][8];
#pragma unroll
    for (int i = 0; i < 2; i++)
#pragma unroll
        for (int j = 0; j < 8; j++) acc[i][j] = make_float4(0.f, 0.f, 0.f, 0.f);

    for (int k0 = 0; k0 < CCH; k0 += 16) {
#pragma unroll
        for (int i = 0; i < 2; i++) {
            int idx = tid + i * 256;
            int row = idx >> 2, kc = (idx & 3) << 2;
            float4 v = *(const float4*)(Wp + (size_t)row * CCH + k0 + kc);
            float4 h, l; split4(v, h, l);
            *(float4*)&AsH[row * SA + kc] = h;
            *(float4*)&AsL[row * SA + kc] = l;

            int kr = idx >> 5, nc = (idx & 31) << 2;
            float4 u = *(const float4*)(Xp + (size_t)(k0 + kr) * NPIX + n0 + nc);
            float4 uh, ul; split4(u, uh, ul);
            *(float4*)&BsH[kr * SB + nc] = uh;
            *(float4*)&BsL[kr * SB + nc] = ul;
        }
        __syncthreads();
#pragma unroll
        for (int ks = 0; ks < 16; ks += 8) {
            uint32_t aH[2][4], aL[2][4];
#pragma unroll
            for (int mt = 0; mt < 2; mt++) {
                int r = (wm * 32 + mt * 16 + lm) * SA + ks + lk;
                aH[mt][0] = __float_as_uint(AsH[r]);
                aH[mt][1] = __float_as_uint(AsH[r + 8 * SA]);
                aH[mt][2] = __float_as_uint(AsH[r + 4]);
                aH[mt][3] = __float_as_uint(AsH[r + 8 * SA + 4]);
                aL[mt][0] = __float_as_uint(AsL[r]);
                aL[mt][1] = __float_as_uint(AsL[r + 8 * SA]);
                aL[mt][2] = __float_as_uint(AsL[r + 4]);
                aL[mt][3] = __float_as_uint(AsL[r + 8 * SA + 4]);
            }
#pragma unroll
            for (int nt = 0; nt < 8; nt++) {
                int cb = (ks + lk) * SB + wn * 64 + nt * 8 + lm;
                uint32_t bH0 = __float_as_uint(BsH[cb]);
                uint32_t bH1 = __float_as_uint(BsH[cb + 4 * SB]);
                uint32_t bL0 = __float_as_uint(BsL[cb]);
                uint32_t bL1 = __float_as_uint(BsL[cb + 4 * SB]);
#pragma unroll
                for (int mt = 0; mt < 2; mt++) {
                    mma8(acc[mt][nt], aH[mt], bH0, bH1);
                    mma8(acc[mt][nt], aH[mt], bL0, bL1);
                    mma8(acc[mt][nt], aL[mt], bH0, bH1);
                }
            }
        }
        __syncthreads();
    }

    float* D = g_logits + ((size_t)(w * BATCH + b) * HD) * NPIX + n0;
#pragma unroll
    for (int mt = 0; mt < 2; mt++)
#pragma unroll
        for (int nt = 0; nt < 8; nt++) {
            int r = wm * 32 + mt * 16 + lm;
            int c = wn * 64 + nt * 8 + 2 * lk;
            *(float2*)(D + (size_t)r * NPIX + c)       = make_float2(acc[mt][nt].x, acc[mt][nt].y);
            *(float2*)(D + (size_t)(r + 8) * NPIX + c) = make_float2(acc[mt][nt].z, acc[mt][nt].w);
        }
}

// ---------------------------------------------------------------------------
// K2: in-place row softmax over N=4096 for w=0 (A) and w=2 (C)
// ---------------------------------------------------------------------------
__global__ void __launch_bounds__(256) k_softmax() {
    int rid = blockIdx.x;                       // 0..4095
    int w = (rid < 2048) ? 0 : 2;
    int r = rid & 2047;                         // b*128 + h
    float* p = g_logits + ((size_t)(w * 2048 + r)) * NPIX;
    int tid = threadIdx.x;
    __shared__ float red[256];

    float4 v[4];
#pragma unroll
    for (int q = 0; q < 4; q++) v[q] = *(float4*)(p + (q * 256 + tid) * 4);

    float m = v[0].x;
#pragma unroll
    for (int q = 0; q < 4; q++) {
        m = fmaxf(m, v[q].x); m = fmaxf(m, v[q].y);
        m = fmaxf(m, v[q].z); m = fmaxf(m, v[q].w);
    }
    red[tid] = m; __syncthreads();
    for (int off = 128; off > 0; off >>= 1) {
        if (tid < off) red[tid] = fmaxf(red[tid], red[tid + off]);
        __syncthreads();
    }
    float M = red[0];
    __syncthreads();

    float ssum = 0.0f;
#pragma unroll
    for (int q = 0; q < 4; q++) {
        v[q].x = expf(v[q].x - M); ssum += v[q].x;
        v[q].y = expf(v[q].y - M); ssum += v[q].y;
        v[q].z = expf(v[q].z - M); ssum += v[q].z;
        v[q].w = expf(v[q].w - M); ssum += v[q].w;
    }
    red[tid] = ssum; __syncthreads();
    for (int off = 128; off > 0; off >>= 1) {
        if (tid < off) red[tid] += red[tid + off];
        __syncthreads();
    }
    float inv = 1.0f / red[0];
#pragma unroll
    for (int q = 0; q < 4; q++) {
        v[q].x *= inv; v[q].y *= inv; v[q].z *= inv; v[q].w *= inv;
        *(float4*)(p + (q * 256 + tid) * 4) = v[q];
    }
}

// ---------------------------------------------------------------------------
// K3: G[b] += Bf[b] (128x4096) @ A[b]^T   [tf32x3 tensor, 8-way k-split]
// M=128 (h), N=128 (g), K slice 512 per CTA
// ---------------------------------------------------------------------------
__global__ void __launch_bounds__(256) k_gemm_G_t() {
    __shared__ float AsH[128 * SA], AsL[128 * SA];   // Bf: [h][k]
    __shared__ float BsH[128 * SA], BsL[128 * SA];   // Am: [g][k]
    const int b  = blockIdx.x;
    const int nb = blockIdx.y * 512;
    const float* Bf = g_logits + ((size_t)(BATCH + b) * HD) * NPIX;   // w=1
    const float* Am = g_logits + ((size_t)b * HD) * NPIX;             // w=0 softmaxed
    const int tid  = threadIdx.x;
    const int lane = tid & 31, wid = tid >> 5;
    const int wm = wid & 3, wn = wid >> 2;
    const int lm = lane >> 2, lk = lane & 3;

    float4 acc[2][8];
#pragma unroll
    for (int i = 0; i < 2; i++)
#pragma unroll
        for (int j = 0; j < 8; j++) acc[i][j] = make_float4(0.f, 0.f, 0.f, 0.f);

    for (int k0 = 0; k0 < 512; k0 += 16) {
#pragma unroll
        for (int i = 0; i < 2; i++) {
            int idx = tid + i * 256;
            int row = idx >> 2, kc = (idx & 3) << 2;
            float4 v = *(const float4*)(Bf + (size_t)row * NPIX + nb + k0 + kc);
            float4 h, l; split4(v, h, l);
            *(float4*)&AsH[row * SA + kc] = h;
            *(float4*)&AsL[row * SA + kc] = l;

            float4 u = *(const float4*)(Am + (size_t)row * NPIX + nb + k0 + kc);
            float4 uh, ul; split4(u, uh, ul);
            *(float4*)&BsH[row * SA + kc] = uh;
            *(float4*)&BsL[row * SA + kc] = ul;
        }
        __syncthreads();
#pragma unroll
        for (int ks = 0; ks < 16; ks += 8) {
            uint32_t aH[2][4], aL[2][4];
#pragma unroll
            for (int mt = 0; mt < 2; mt++) {
                int r = (wm * 32 + mt * 16 + lm) * SA + ks + lk;
                aH[mt][0] = __float_as_uint(AsH[r]);
                aH[mt][1] = __float_as_uint(AsH[r + 8 * SA]);
                aH[mt][2] = __float_as_uint(AsH[r + 4]);
                aH[mt][3] = __float_as_uint(AsH[r + 8 * SA + 4]);
                aL[mt][0] = __float_as_uint(AsL[r]);
                aL[mt][1] = __float_as_uint(AsL[r + 8 * SA]);
                aL[mt][2] = __float_as_uint(AsL[r + 4]);
                aL[mt][3] = __float_as_uint(AsL[r + 8 * SA + 4]);
            }
#pragma unroll
            for (int nt = 0; nt < 8; nt++) {
                int cb = (wn * 64 + nt * 8 + lm) * SA + ks + lk;
                uint32_t bH0 = __float_as_uint(BsH[cb]);
                uint32_t bH1 = __float_as_uint(BsH[cb + 4]);
                uint32_t bL0 = __float_as_uint(BsL[cb]);
                uint32_t bL1 = __float_as_uint(BsL[cb + 4]);
#pragma unroll
                for (int mt = 0; mt < 2; mt++) {
                    mma8(acc[mt][nt], aH[mt], bH0, bH1);
                    mma8(acc[mt][nt], aH[mt], bL0, bL1);
                    mma8(acc[mt][nt], aL[mt], bH0, bH1);
                }
            }
        }
        __syncthreads();
    }

    float* Gp = g_G + (size_t)b * HD * HD;
#pragma unroll
    for (int mt = 0; mt < 2; mt++)
#pragma unroll
        for (int nt = 0; nt < 8; nt++) {
            int r = wm * 32 + mt * 16 + lm;
            int c = wn * 64 + nt * 8 + 2 * lk;
            atomicAdd(&Gp[r * HD + c],           acc[mt][nt].x);
            atomicAdd(&Gp[r * HD + c + 1],       acc[mt][nt].y);
            atomicAdd(&Gp[(r + 8) * HD + c],     acc[mt][nt].z);
            atomicAdd(&Gp[(r + 8) * HD + c + 1], acc[mt][nt].w);
        }
}

// ---------------------------------------------------------------------------
// K4: M2[b][c][g] = s[c] * sum_h wProj[c][h] * G[b][h][g]
// ---------------------------------------------------------------------------
__global__ void __launch_bounds__(128) k_M2(const float* __restrict__ wProj) {
    const int b = blockIdx.x, c = blockIdx.y, g = threadIdx.x;
    __shared__ float wrow[HD];
    wrow[g] = wProj[(size_t)c * HD + g];
    __syncthreads();
    const float* Gp = g_G + (size_t)b * HD * HD;
    float acc = 0.0f;
#pragma unroll 8
    for (int h = 0; h < HD; h++) acc = fmaf(wrow[h], Gp[h * HD + g], acc);
    g_M2[((size_t)b * CCH + c) * HD + g] = g_s[c] * acc;
}

// ---------------------------------------------------------------------------
// K5: out[b] = M2[b] (512x128) @ Cs[b] (128x4096) + t[c]   [tf32x3 tensor]
// ---------------------------------------------------------------------------
__global__ void __launch_bounds__(256) k_gemm_out_t(float* __restrict__ out) {
    __shared__ float AsH[128 * SA], AsL[128 * SA];   // M2 tile [c][g]
    __shared__ float BsH[16 * SB],  BsL[16 * SB];    // Cs tile [g][n]
    const int b  = blockIdx.z;
    const int c0 = blockIdx.y * 128;
    const int n0 = blockIdx.x * 128;
    const float* Ap = g_M2 + (size_t)b * CCH * HD;
    const float* Cs = g_logits + ((size_t)(2 * BATCH + b) * HD) * NPIX; // w=2 softmaxed
    const int tid  = threadIdx.x;
    const int lane = tid & 31, wid = tid >> 5;
    const int wm = wid & 3, wn = wid >> 2;
    const int lm = lane >> 2, lk = lane & 3;

    float4 acc[2][8];
#pragma unroll
    for (int i = 0; i < 2; i++)
#pragma unroll
        for (int j = 0; j < 8; j++) acc[i][j] = make_float4(0.f, 0.f, 0.f, 0.f);

    for (int k0 = 0; k0 < HD; k0 += 16) {
#pragma unroll
        for (int i = 0; i < 2; i++) {
            int idx = tid + i * 256;
            int row = idx >> 2, kc = (idx & 3) << 2;
            float4 v = *(const float4*)(Ap + (size_t)(c0 + row) * HD + k0 + kc);
            float4 h, l; split4(v, h, l);
            *(float4*)&AsH[row * SA + kc] = h;
            *(float4*)&AsL[row * SA + kc] = l;

            int kr = idx >> 5, nc = (idx & 31) << 2;
            float4 u = *(const float4*)(Cs + (size_t)(k0 + kr) * NPIX + n0 + nc);
            float4 uh, ul; split4(u, uh, ul);
            *(float4*)&BsH[kr * SB + nc] = uh;
            *(float4*)&BsL[kr * SB + nc] = ul;
        }
        __syncthreads();
#pragma unroll
        for (int ks = 0; ks < 16; ks += 8) {
            uint32_t aH[2][4], aL[2][4];
#pragma unroll
            for (int mt = 0; mt < 2; mt++) {
                int r = (wm * 32 + mt * 16 + lm) * SA + ks + lk;
                aH[mt][0] = __float_as_uint(AsH[r]);
                aH[mt][1] = __float_as_uint(AsH[r + 8 * SA]);
                aH[mt][2] = __float_as_uint(AsH[r + 4]);
                aH[mt][3] = __float_as_uint(AsH[r + 8 * SA + 4]);
                aL[mt][0] = __float_as_uint(AsL[r]);
                aL[mt][1] = __float_as_uint(AsL[r + 8 * SA]);
                aL[mt][2] = __float_as_uint(AsL[r + 4]);
                aL[mt][3] = __float_as_uint(AsL[r + 8 * SA + 4]);
            }
#pragma unroll
            for (int nt = 0; nt < 8; nt++) {
                int cb = (ks + lk) * SB + wn * 64 + nt * 8 + lm;
                uint32_t bH0 = __float_as_uint(BsH[cb]);
                uint32_t bH1 = __float_as_uint(BsH[cb + 4 * SB]);
                uint32_t bL0 = __float_as_uint(BsL[cb]);
                uint32_t bL1 = __float_as_uint(BsL[cb + 4 * SB]);
#pragma unroll
                for (int mt = 0; mt < 2; mt++) {
                    mma8(acc[mt][nt], aH[mt], bH0, bH1);
                    mma8(acc[mt][nt], aH[mt], bL0, bL1);
                    mma8(acc[mt][nt], aL[mt], bH0, bH1);
                }
            }
        }
        __syncthreads();
    }

#pragma unroll
    for (int mt = 0; mt < 2; mt++)
#pragma unroll
        for (int nt = 0; nt < 8; nt++) {
            int r = wm * 32 + mt * 16 + lm;
            int c = wn * 64 + nt * 8 + 2 * lk;
            float t0 = g_t[c0 + r];
            float t1 = g_t[c0 + r + 8];
            float* D0 = out + ((size_t)b * CCH + c0 + r) * NPIX + n0 + c;
            float* D1 = out + ((size_t)b * CCH + c0 + r + 8) * NPIX + n0 + c;
            *(float2*)D0 = make_float2(acc[mt][nt].x + t0, acc[mt][nt].y + t0);
            *(float2*)D1 = make_float2(acc[mt][nt].z + t1, acc[mt][nt].w + t1);
        }
}

// ---------------------------------------------------------------------------
extern "C" void kernel_launch(void* const* d_in, const int* in_sizes, int n_in,
                              void* d_out, int out_size) {
    const float* x     = (const float*)d_in[0];
    const float* wA    = (const float*)d_in[1];
    const float* wB    = (const float*)d_in[2];
    const float* wC    = (const float*)d_in[3];
    const float* wProj = (const float*)d_in[4];
    const float* gamma = (const float*)d_in[5];
    const float* beta  = (const float*)d_in[6];
    const float* mean  = (const float*)d_in[7];
    const float* var   = (const float*)d_in[8];
    float* out = (float*)d_out;

    k_prep<<<1024, 256>>>(gamma, beta, mean, var);
    k_gemm_logits_t<<<dim3(32, 3, BATCH), 256>>>(x, wA, wB, wC);
    k_softmax<<<4096, 256>>>();
    k_gemm_G_t<<<dim3(BATCH, 8), 256>>>();
    k_M2<<<dim3(BATCH, CCH), 128>>>(wProj);
    k_gemm_out_t<<<dim3(32, 4, BATCH), 256>>>(out);
}